// round 15
// baseline (speedup 1.0000x reference)
#include <cuda_runtime.h>
#include <cuda_bf16.h>
#include <cstdint>

// ---------------------------------------------------------------------------
// Fused Upsampling MLP via warp-level HMMA (mma.sync m16n8k16 bf16, fp32 acc),
// bf16x3 split (hi*hi + lo*hi + hi*lo) for fp32-level accuracy.
// Round 15: 512 threads / 16 warps (4M x 4N, warp tile 32x32) for 4 warps/SMSP
// latency hiding; B fragments via ldmatrix.x4.trans (halved LDSM count);
// cp.async double-buffered pipeline over 8 unified phases (A: gathered
// x_down @ W_lin; B: [x_up,H] @ W_fus, phases 6-7 consume H from smem).
// Baseline ISA only (harness PTX target is sm_103, no 'a').
// ---------------------------------------------------------------------------

#define C_DOWN 256
#define C_UP   128
#define N_DOWN 16384
#define TMROWS 128
#define THREADS 512

// smem layout (all regions 1024B-aligned for SW128 swizzle)
#define SM_GB    0                        // 128 x int64 gather bases (1KB)
#define SM_RAW   1024                     // raw fp32 A staging, 2 bufs x 32KB
#define SM_A     (SM_RAW + 65536)         // A tiles: hi 16KB + lo 16KB (single)
#define SM_B     (SM_A + 32768)           // B blob, 2 bufs x 32KB
#define SM_H     (SM_B + 65536)           // H: 2 chunks x (hi 16KB + lo 16KB)
#define SMEM_TOTAL (SM_H + 65536)         // 230400 B (<= 227KB opt-in)

#define SWZ(o) ((o) ^ (((o) >> 3) & 0x70))

// Pre-split, pre-swizzled weights. Per chunk c (64 K): [hi: n-half0, n-half1][lo: ...]
// Each half tile: [64 k][64 n] bf16, 128B rows, SW128.
__device__ __align__(1024) unsigned char g_wlin[131072];
__device__ __align__(1024) unsigned char g_wfus[131072];

// ------------------------------- helpers -----------------------------------
__device__ __forceinline__ uint32_t smem_u32(const void* p) {
    uint32_t a;
    asm("{ .reg .u64 t; cvta.to.shared.u64 t, %1; cvt.u32.u64 %0, t; }"
        : "=r"(a) : "l"(p));
    return a;
}
__device__ __forceinline__ void cpasync16(uint32_t dst, const void* src) {
    asm volatile("cp.async.cg.shared.global [%0], [%1], 16;"
                 :: "r"(dst), "l"(src) : "memory");
}
__device__ __forceinline__ void cp_commit() {
    asm volatile("cp.async.commit_group;" ::: "memory");
}
template<int N> __device__ __forceinline__ void cp_wait() {
    asm volatile("cp.async.wait_group %0;" :: "n"(N) : "memory");
}
__device__ __forceinline__ void ldsm4(uint32_t* r, uint32_t a) {
    asm volatile("ldmatrix.sync.aligned.m8n8.x4.shared.b16 {%0,%1,%2,%3}, [%4];"
                 : "=r"(r[0]), "=r"(r[1]), "=r"(r[2]), "=r"(r[3]) : "r"(a));
}
__device__ __forceinline__ void ldsm4t(uint32_t* r, uint32_t a) {
    asm volatile("ldmatrix.sync.aligned.m8n8.x4.trans.shared.b16 {%0,%1,%2,%3}, [%4];"
                 : "=r"(r[0]), "=r"(r[1]), "=r"(r[2]), "=r"(r[3]) : "r"(a));
}
__device__ __forceinline__ void mma_bf16(float* d, const uint32_t* a, const uint32_t* b) {
    asm volatile("mma.sync.aligned.m16n8k16.row.col.f32.bf16.bf16.f32 "
                 "{%0,%1,%2,%3},{%4,%5,%6,%7},{%8,%9},{%0,%1,%2,%3};"
                 : "+f"(d[0]), "+f"(d[1]), "+f"(d[2]), "+f"(d[3])
                 : "r"(a[0]), "r"(a[1]), "r"(a[2]), "r"(a[3]),
                   "r"(b[0]), "r"(b[1]));
}
// split fp32 pair -> packed bf16x2 hi and lo
__device__ __forceinline__ uint32_t split2(float a, float b, uint32_t& lo_out) {
    __nv_bfloat16 ha = __float2bfloat16(a), hb = __float2bfloat16(b);
    __nv_bfloat16 la = __float2bfloat16(a - __bfloat162float(ha));
    __nv_bfloat16 lb = __float2bfloat16(b - __bfloat162float(hb));
    lo_out = ((uint32_t)__bfloat16_as_ushort(lb) << 16) | __bfloat16_as_ushort(la);
    return ((uint32_t)__bfloat16_as_ushort(hb) << 16) | __bfloat16_as_ushort(ha);
}

// ----------------------------- weight pack kernel ---------------------------
__global__ void pack_w(const float* __restrict__ Wlin, const float* __restrict__ Wfus) {
    int i = blockIdx.x * blockDim.x + threadIdx.x;    // 0..32767 over [K=256][N=128]
    if (i >= 32768) return;
    int k = i >> 7, n = i & 127;
    int c = k >> 6, kk = k & 63;
    int half = n >> 6, nn = n & 63;
    uint32_t sw = SWZ((uint32_t)kk * 128u + (uint32_t)nn * 2u);
    uint32_t base = (uint32_t)c * 32768u + (uint32_t)half * 8192u;
    {
        float w = Wlin[i];
        __nv_bfloat16 hi = __float2bfloat16(w);
        __nv_bfloat16 lo = __float2bfloat16(w - __bfloat162float(hi));
        *(__nv_bfloat16*)(g_wlin + base + sw)         = hi;
        *(__nv_bfloat16*)(g_wlin + base + 16384 + sw) = lo;
    }
    {
        float w = Wfus[i];
        __nv_bfloat16 hi = __float2bfloat16(w);
        __nv_bfloat16 lo = __float2bfloat16(w - __bfloat162float(hi));
        *(__nv_bfloat16*)(g_wfus + base + sw)         = hi;
        *(__nv_bfloat16*)(g_wfus + base + 16384 + sw) = lo;
    }
}

// --------------------- per-chunk warp MMA (64 K-values) ---------------------
// Warp tile 32(M) x 32(N): 2 mt x 4 nt m16n8k16 tiles, 3 split passes each.
// bBaseHi points at the warp's B half (8KB hi tile); col offsets go through SWZ.
__device__ __forceinline__ void compute_chunk(float acc[2][4][4],
                                              uint32_t aHi, uint32_t aLo,
                                              uint32_t bBaseHi, uint32_t bColByte,
                                              int lane, int warpMrow)
{
    const uint32_t csel = (lane & 16) ? 16u : 0u;
    const int arow = warpMrow + (lane & 15);
    const uint32_t blane = bColByte + (uint32_t)((lane >> 4) & 1) * 16u;  // x4t col sel
#pragma unroll
    for (int kb = 0; kb < 64; kb += 16) {
        uint32_t ah[2][4], al[2][4];
#pragma unroll
        for (int mt = 0; mt < 2; mt++) {
            uint32_t sw = SWZ((uint32_t)(arow + mt * 16) * 128u + (uint32_t)kb * 2u + csel);
            ldsm4(ah[mt], aHi + sw);
            ldsm4(al[mt], aLo + sw);
        }
        const uint32_t brow = (uint32_t)(kb + (lane & 15)) * 128u;
#pragma unroll
        for (int ntp = 0; ntp < 2; ntp++) {
            // x4.trans: lanes 0-15 -> nt=2*ntp, lanes 16-31 -> nt=2*ntp+1
            uint32_t sw = SWZ(brow + blane + (uint32_t)ntp * 32u);
            uint32_t bh[4], bl[4];
            ldsm4t(bh, bBaseHi + sw);
            ldsm4t(bl, bBaseHi + 16384u + sw);
#pragma unroll
            for (int sub = 0; sub < 2; sub++) {
                const int nt = ntp * 2 + sub;
#pragma unroll
                for (int mt = 0; mt < 2; mt++) {
                    mma_bf16(acc[mt][nt], ah[mt], bh + sub * 2);   // hi*hi
                    mma_bf16(acc[mt][nt], al[mt], bh + sub * 2);   // lo*hi
                    mma_bf16(acc[mt][nt], ah[mt], bl + sub * 2);   // hi*lo
                }
            }
        }
    }
}

// ------------------------------- main kernel --------------------------------
__global__ void __launch_bounds__(THREADS, 1)
mlp_tc_kernel(const float* __restrict__ x_down,
              const float* __restrict__ x_up,
              const int* __restrict__ up_idx,
              const float* __restrict__ b_lin,
              const float* __restrict__ b_fus,
              float* __restrict__ out,
              long long n_up_per_batch)
{
    extern __shared__ __align__(1024) char smem[];
    const uint32_t sb = smem_u32(smem);
    const int tid  = threadIdx.x;
    const int wid  = tid >> 5;
    const int lane = tid & 31;
    const int warp_m = wid & 3;      // 32-row slice
    const int warp_n = wid >> 2;     // 32-col slice (0..3)
    const int warpMrow = warp_m * 32;
    const int gid = lane >> 2, tig = lane & 3;
    const long long p0 = (long long)blockIdx.x * TMROWS;

    long long* gbase = (long long*)(smem + SM_GB);
    if (tid < TMROWS) {
        long long p = p0 + tid;
        long long b = p / n_up_per_batch;
        gbase[tid] = (b * N_DOWN + (long long)up_idx[p]) * C_DOWN;
    }
    __syncthreads();   // gbase ready before any prefetch

    float acc[2][4][4];
#pragma unroll
    for (int a = 0; a < 2; a++)
#pragma unroll
        for (int b = 0; b < 4; b++)
#pragma unroll
            for (int c = 0; c < 4; c++) acc[a][b][c] = 0.f;

    // ---- prefetch: raw fp32 A chunk (ph<6) + pre-split B blob -> buf ----
    auto prefetch = [&](int ph, int buf) {
        const unsigned char* wsrc = ((ph < 4) ? g_wlin : g_wfus) + (ph & 3) * 32768;
        const uint32_t bdst = sb + SM_B + (uint32_t)buf * 32768u;
#pragma unroll
        for (int u = 0; u < 4; u++) {
            int s = tid + u * 512;
            cpasync16(bdst + (uint32_t)s * 16u, wsrc + s * 16);
        }
        if (ph < 6) {
            const int c = ph & 3;
            const uint32_t rdst = sb + SM_RAW + (uint32_t)buf * 32768u;
#pragma unroll
            for (int u = 0; u < 4; u++) {
                int s = tid + u * 512;
                int r = s >> 4, sg = s & 15;
                const float* src = (ph < 4)
                    ? (x_down + gbase[r] + c * 64 + sg * 4)
                    : (x_up + (p0 + r) * C_UP + c * 64 + sg * 4);
                cpasync16(rdst + (uint32_t)s * 16u, src);
            }
        }
    };

    prefetch(0, 0);
    cp_commit();

    // warp's B addressing: half (64n) + 32-col offset within half
    const uint32_t bColByte = (uint32_t)(warp_n & 1) * 64u;

    for (int ph = 0; ph < 8; ph++) {
        const int buf = ph & 1;
        if (ph < 7) { prefetch(ph + 1, buf ^ 1); cp_commit(); }
        if (ph < 7) cp_wait<1>(); else cp_wait<0>();
        __syncthreads();                       // chunk ph copies visible

        uint32_t aHi, aLo;
        if (ph < 6) {
            // convert raw fp32 -> bf16 hi/lo SW128 tiles (512 threads: 16 f/thread)
            const int row = tid >> 2;          // 0..127
            const int q   = tid & 3;           // 16-float quarter
            const float* src = (const float*)(smem + SM_RAW + buf * 32768)
                               + row * 64 + q * 16;
            const uint32_t rbase = (uint32_t)row * 128u + (uint32_t)q * 32u;
#pragma unroll
            for (int i = 0; i < 4; i++) {
                float4 v = *reinterpret_cast<const float4*>(src + i * 4);
                uint32_t lo0, lo1;
                uint32_t hi0 = split2(v.x, v.y, lo0);
                uint32_t hi1 = split2(v.z, v.w, lo1);
                uint32_t sw = SWZ(rbase + i * 8u);
                *(uint2*)(smem + SM_A + sw)          = make_uint2(hi0, hi1);
                *(uint2*)(smem + SM_A + 16384 + sw)  = make_uint2(lo0, lo1);
            }
            __syncthreads();                   // tiles visible to all warps
            aHi = sb + SM_A;
            aLo = aHi + 16384u;
        } else {
            aHi = sb + SM_H + (uint32_t)(ph - 6) * 32768u;
            aLo = aHi + 16384u;
        }

        const uint32_t bBaseHi = sb + SM_B + (uint32_t)buf * 32768u
                               + (uint32_t)(warp_n >> 1) * 8192u;
        compute_chunk(acc, aHi, aLo, bBaseHi, bColByte, lane, warpMrow);

        if (ph == 3) {
            // Epilogue A: bias + leaky -> H tiles (bf16 hi/lo, SW128), reset acc.
#pragma unroll
            for (int mt = 0; mt < 2; mt++)
#pragma unroll
                for (int nt = 0; nt < 4; nt++) {
                    int col = warp_n * 32 + nt * 8 + 2 * tig;
                    int hc = col >> 6, kk = col & 63;
                    float bb0 = b_lin[col], bb1 = b_lin[col + 1];
                    unsigned char* hbase = (unsigned char*)smem + SM_H + hc * 32768;
#pragma unroll
                    for (int rr = 0; rr < 2; rr++) {
                        int r = warpMrow + mt * 16 + gid + rr * 8;
                        float v0 = acc[mt][nt][rr * 2]     + bb0;
                        float v1 = acc[mt][nt][rr * 2 + 1] + bb1;
                        v0 = (v0 >= 0.f) ? v0 : 0.1f * v0;
                        v1 = (v1 >= 0.f) ? v1 : 0.1f * v1;
                        uint32_t sw = SWZ((uint32_t)r * 128u + (uint32_t)kk * 2u);
                        uint32_t lo;
                        uint32_t hi = split2(v0, v1, lo);
                        *(uint32_t*)(hbase + sw)         = hi;
                        *(uint32_t*)(hbase + 16384 + sw) = lo;
                        acc[mt][nt][rr * 2]     = 0.f;
                        acc[mt][nt][rr * 2 + 1] = 0.f;
                    }
                }
        }
        __syncthreads();   // compute(ph) reads done before prefetch(ph+2) refills buf
    }

    // Epilogue B: bias + leaky -> out (fp32 pairs)
#pragma unroll
    for (int mt = 0; mt < 2; mt++)
#pragma unroll
        for (int nt = 0; nt < 4; nt++) {
            int col = warp_n * 32 + nt * 8 + 2 * tig;
            float bb0 = b_fus[col], bb1 = b_fus[col + 1];
#pragma unroll
            for (int rr = 0; rr < 2; rr++) {
                long long r = p0 + warpMrow + mt * 16 + gid + rr * 8;
                float v0 = acc[mt][nt][rr * 2]     + bb0;
                float v1 = acc[mt][nt][rr * 2 + 1] + bb1;
                v0 = (v0 >= 0.f) ? v0 : 0.1f * v0;
                v1 = (v1 >= 0.f) ? v1 : 0.1f * v1;
                *reinterpret_cast<float2*>(out + r * 128 + col) = make_float2(v0, v1);
            }
        }
}

// ------------------------------- launch -------------------------------------
extern "C" void kernel_launch(void* const* d_in, const int* in_sizes, int n_in,
                              void* d_out, int out_size)
{
    const float* x_down = (const float*)d_in[0];
    const float* x_up   = (const float*)d_in[1];
    const int*   up_idx = (const int*)d_in[2];      // int32 (JAX x64 off)
    const float* W_lin  = (const float*)d_in[3];
    const float* b_lin  = (const float*)d_in[4];
    const float* W_fus  = (const float*)d_in[5];
    const float* b_fus  = (const float*)d_in[6];
    float*       out    = (float*)d_out;

    const long long total_rows = in_sizes[2];                         // B * N_up
    const long long B          = (long long)in_sizes[0] / ((long long)N_DOWN * C_DOWN);
    const long long n_up_pb    = total_rows / B;

    cudaFuncSetAttribute(mlp_tc_kernel,
                         cudaFuncAttributeMaxDynamicSharedMemorySize, SMEM_TOTAL);

    pack_w<<<128, 256>>>(W_lin, W_fus);

    const int grid = (int)(total_rows / TMROWS);
    mlp_tc_kernel<<<grid, THREADS, SMEM_TOTAL>>>(x_down, x_up, up_idx,
                                                 b_lin, b_fus, out, n_up_pb);
}